// round 9
// baseline (speedup 1.0000x reference)
#include <cuda_runtime.h>
#include <cuda_fp16.h>
#include <mma.h>
#include <math.h>

using namespace nvcuda;

#define N_NODES 100000
#define N_EDGES 1200000
#define COL_CAP (N_EDGES + 3 * N_NODES + 16)
#define HID 64
#define G_NUM 128
#define C_OUT 10
#define D_IN 3
#define EPS_BN 1e-5f

static __device__ __forceinline__ unsigned int h2_bits(__half2 h) {
    return *reinterpret_cast<unsigned int*>(&h);
}
static __device__ __forceinline__ __half2 bits_h2(unsigned int u) {
    return *reinterpret_cast<__half2*>(&u);
}

// -------- scratch (static device globals; no runtime allocation) --------
__device__ int   g_ecnt[N_NODES];
__device__ int   g_base[N_NODES];     // after k_base: aligned start; after k_fill: start+cnt
__device__ __align__(16) int g_col[COL_CAP];
__device__ int   g_tot;
__device__ float g_dinv[N_NODES];
__device__ __align__(16) __half g_xwh[N_NODES * HID];   // (h@W)*dinv, fp16
__device__ __align__(16) __half g_hh [N_NODES * HID];   // layer output, fp16

// -------- in-degree over real edges (8 edges/thread) --------
__global__ void __launch_bounds__(256) k_deg(const int* __restrict__ ei) {
    int idx = blockIdx.x * blockDim.x + threadIdx.x;           // < E/8
    if (idx >= N_EDGES / 8) return;
    const int4* dp = (const int4*)(ei + N_EDGES);
    int4 d0 = dp[2 * idx];
    int4 d1 = dp[2 * idx + 1];
    atomicAdd(&g_ecnt[d0.x], 1); atomicAdd(&g_ecnt[d0.y], 1);
    atomicAdd(&g_ecnt[d0.z], 1); atomicAdd(&g_ecnt[d0.w], 1);
    atomicAdd(&g_ecnt[d1.x], 1); atomicAdd(&g_ecnt[d1.y], 1);
    atomicAdd(&g_ecnt[d1.z], 1); atomicAdd(&g_ecnt[d1.w], 1);
}

// -------- dinv + CSR bases, 4-aligned allocations (warp scan + atomic) --------
__global__ void k_base() {
    int i = blockIdx.x * blockDim.x + threadIdx.x;
    int lane = threadIdx.x & 31;
    int c = (i < N_NODES) ? g_ecnt[i] : 0;
    if (i < N_NODES) g_dinv[i] = rsqrtf((float)(c + 1));
    int alloc = (c + 3) & ~3;          // pad to multiple of 4 -> 16B-aligned segments
    int incl = alloc;
    #pragma unroll
    for (int off = 1; off < 32; off <<= 1) {
        int v = __shfl_up_sync(0xffffffffu, incl, off);
        if (lane >= off) incl += v;
    }
    int excl = incl - alloc;
    int wsum = __shfl_sync(0xffffffffu, incl, 31);
    int wbase = 0;
    if (lane == 31) wbase = atomicAdd(&g_tot, wsum);
    wbase = __shfl_sync(0xffffffffu, wbase, 31);
    if (i < N_NODES) g_base[i] = wbase + excl;
}

// -------- CSR fill: cursor IS g_base; 8 edges/thread for MLP ------
__global__ void __launch_bounds__(256) k_fill(const int* __restrict__ ei) {
    int idx = blockIdx.x * blockDim.x + threadIdx.x;           // < E/8
    if (idx >= N_EDGES / 8) return;
    const int4* sp = (const int4*)ei;
    const int4* dp = (const int4*)(ei + N_EDGES);
    int4 s0 = sp[2 * idx], s1 = sp[2 * idx + 1];
    int4 d0 = dp[2 * idx], d1 = dp[2 * idx + 1];
    int p0 = atomicAdd(&g_base[d0.x], 1);
    int p1 = atomicAdd(&g_base[d0.y], 1);
    int p2 = atomicAdd(&g_base[d0.z], 1);
    int p3 = atomicAdd(&g_base[d0.w], 1);
    int p4 = atomicAdd(&g_base[d1.x], 1);
    int p5 = atomicAdd(&g_base[d1.y], 1);
    int p6 = atomicAdd(&g_base[d1.z], 1);
    int p7 = atomicAdd(&g_base[d1.w], 1);
    g_col[p0] = s0.x; g_col[p1] = s0.y; g_col[p2] = s0.z; g_col[p3] = s0.w;
    g_col[p4] = s1.x; g_col[p5] = s1.y; g_col[p6] = s1.z; g_col[p7] = s1.w;
}

// -------- layer 0 linear: x[N,3] @ W0[3,64] * dinv -> fp16, 4 cols/thread -----
__global__ void __launch_bounds__(256) k_lin0(const float* __restrict__ x,
                                              const float* __restrict__ W0) {
    __shared__ float sW[D_IN * HID];
    int t = threadIdx.x;
    if (t < D_IN * HID) sW[t] = W0[t];
    __syncthreads();
    int idx = blockIdx.x * blockDim.x + t;                     // < N*16
    if (idx >= N_NODES * 16) return;
    int i = idx >> 4, j4 = idx & 15;
    float x0 = x[i * 3 + 0], x1 = x[i * 3 + 1], x2 = x[i * 3 + 2];
    float d = g_dinv[i];
    float o[4];
    #pragma unroll
    for (int q = 0; q < 4; q++) {
        int j = 4 * j4 + q;
        o[q] = (x0 * sW[j] + x1 * sW[64 + j] + x2 * sW[128 + j]) * d;
    }
    uint2 pk;
    pk.x = h2_bits(__floats2half2_rn(o[0], o[1]));
    pk.y = h2_bits(__floats2half2_rn(o[2], o[3]));
    ((uint2*)g_xwh)[idx] = pk;
}

// -------- hidden linear via WMMA: 128 nodes x 64 cols / block, 8 warps --------
// A = h[i]*dinv[i] (fp16), B = W (fp16), C = fp32 accum -> fp16 g_xwh
__global__ void __launch_bounds__(256) k_linh(const float* __restrict__ W) {
    __shared__ __align__(16) char smem[32768];
    __half* sA = (__half*)smem;              // [128][64] fp16, 16KB
    __half* sB = (__half*)(smem + 16384);    // [64][64]  fp16,  8KB
    float*  sO = (float*)smem;               // [128][64] fp32, 32KB (reused after sync)

    int t = threadIdx.x;
    int warp = t >> 5;
    int node0 = blockIdx.x * 128;

    // W -> sB fp16
    for (int q = t; q < HID * HID; q += 256) sB[q] = __float2half(W[q]);

    // h rows * dinv -> sA fp16 (rows 128B = 16 uint2 each)
    for (int q = t; q < 128 * 16; q += 256) {
        int r = q >> 4, c8 = q & 15;
        int gi = node0 + r;
        uint2 pk = make_uint2(0u, 0u);
        if (gi < N_NODES) {
            uint2 v = ((const uint2*)g_hh)[gi * 16 + c8];
            __half2 dd = __float2half2_rn(g_dinv[gi]);
            pk.x = h2_bits(__hmul2(bits_h2(v.x), dd));
            pk.y = h2_bits(__hmul2(bits_h2(v.y), dd));
        }
        ((uint2*)sA)[q] = pk;
    }
    __syncthreads();

    // each warp: 16 rows x 64 cols
    wmma::fragment<wmma::accumulator, 16, 16, 16, float> fc[4];
    #pragma unroll
    for (int n = 0; n < 4; n++) wmma::fill_fragment(fc[n], 0.0f);

    #pragma unroll
    for (int k = 0; k < 4; k++) {
        wmma::fragment<wmma::matrix_a, 16, 16, 16, __half, wmma::row_major> fa;
        wmma::load_matrix_sync(fa, sA + (warp * 16) * HID + k * 16, HID);
        #pragma unroll
        for (int n = 0; n < 4; n++) {
            wmma::fragment<wmma::matrix_b, 16, 16, 16, __half, wmma::row_major> fb;
            wmma::load_matrix_sync(fb, sB + (k * 16) * HID + n * 16, HID);
            wmma::mma_sync(fc[n], fa, fb, fc[n]);
        }
    }
    __syncthreads();   // done reading sA/sB; reuse as sO

    #pragma unroll
    for (int n = 0; n < 4; n++)
        wmma::store_matrix_sync(sO + (warp * 16) * HID + n * 16, fc[n], HID,
                                wmma::mem_row_major);
    __syncthreads();

    // pack sO fp32 -> g_xwh fp16
    for (int q = t; q < 128 * 16; q += 256) {
        int r = q >> 4, c8 = q & 15;
        int gi = node0 + r;
        if (gi < N_NODES) {
            float4 v = ((const float4*)sO)[q];
            uint2 pk;
            pk.x = h2_bits(__floats2half2_rn(v.x, v.y));
            pk.y = h2_bits(__floats2half2_rn(v.z, v.w));
            ((uint2*)g_xwh)[gi * 16 + c8] = pk;
        }
    }
}

// -------- CSR gather: int4 cols + half2 tree accum + fused BN -> fp16 h -------
__global__ void __launch_bounds__(256) k_gather(const float* __restrict__ bb,
                                                const float* __restrict__ gamma,
                                                const float* __restrict__ beta,
                                                const float* __restrict__ mean,
                                                const float* __restrict__ var, int relu) {
    int t = threadIdx.x;
    int node = blockIdx.x * 16 + (t >> 4);   // N divisible by 16
    int j4 = t & 15;
    const uint2* xw2 = (const uint2*)g_xwh;

    int cnt  = g_ecnt[node];
    int base = g_base[node] - cnt;           // start (4-aligned)

    uint2 self = xw2[node * 16 + j4];
    float2 slo = __half22float2(bits_h2(self.x));
    float2 shi = __half22float2(bits_h2(self.y));
    float4 acc = make_float4(slo.x, slo.y, shi.x, shi.y);

    const int4* c4p = (const int4*)(g_col + base);   // 16B-aligned
    int k = 0;
    for (; k + 4 <= cnt; k += 4) {
        int4 c4 = __ldg(&c4p[k >> 2]);
        uint2 r0 = __ldg(&xw2[c4.x * 16 + j4]);
        uint2 r1 = __ldg(&xw2[c4.y * 16 + j4]);
        uint2 r2 = __ldg(&xw2[c4.z * 16 + j4]);
        uint2 r3 = __ldg(&xw2[c4.w * 16 + j4]);
        __half2 lo = __hadd2(__hadd2(bits_h2(r0.x), bits_h2(r1.x)),
                             __hadd2(bits_h2(r2.x), bits_h2(r3.x)));
        __half2 hi = __hadd2(__hadd2(bits_h2(r0.y), bits_h2(r1.y)),
                             __hadd2(bits_h2(r2.y), bits_h2(r3.y)));
        float2 flo = __half22float2(lo);
        float2 fhi = __half22float2(hi);
        acc.x += flo.x; acc.y += flo.y; acc.z += fhi.x; acc.w += fhi.y;
    }
    for (; k < cnt; k++) {
        int s = __ldg(&g_col[base + k]);
        uint2 r = __ldg(&xw2[s * 16 + j4]);
        float2 a = __half22float2(bits_h2(r.x));
        float2 b = __half22float2(bits_h2(r.y));
        acc.x += a.x; acc.y += a.y; acc.z += b.x; acc.w += b.y;
    }

    float d = g_dinv[node];
    float4 vb  = ((const float4*)bb)[j4];
    float4 vg  = ((const float4*)gamma)[j4];
    float4 vbt = ((const float4*)beta)[j4];
    float4 vm  = ((const float4*)mean)[j4];
    float4 vv  = ((const float4*)var)[j4];
    float4 o;
    o.x = (acc.x * d + vb.x - vm.x) * (vg.x * rsqrtf(vv.x + EPS_BN)) + vbt.x;
    o.y = (acc.y * d + vb.y - vm.y) * (vg.y * rsqrtf(vv.y + EPS_BN)) + vbt.y;
    o.z = (acc.z * d + vb.z - vm.z) * (vg.z * rsqrtf(vv.z + EPS_BN)) + vbt.z;
    o.w = (acc.w * d + vb.w - vm.w) * (vg.w * rsqrtf(vv.w + EPS_BN)) + vbt.w;
    if (relu) {
        o.x = fmaxf(o.x, 0.f); o.y = fmaxf(o.y, 0.f);
        o.z = fmaxf(o.z, 0.f); o.w = fmaxf(o.w, 0.f);
    }
    uint2 pk;
    pk.x = h2_bits(__floats2half2_rn(o.x, o.y));
    pk.y = h2_bits(__floats2half2_rn(o.z, o.w));
    ((uint2*)g_hh)[node * 16 + j4] = pk;
}

// -------- fused pooling + classifier + log_softmax: 1 block / graph -----------
__global__ void __launch_bounds__(256) k_poolcls(const int* __restrict__ batch,
                                                 const float* __restrict__ Wc1,
                                                 const float* __restrict__ bc1,
                                                 const float* __restrict__ Wc2,
                                                 const float* __restrict__ bc2,
                                                 float* __restrict__ out) {
    __shared__ int s_se[2];
    __shared__ float ssum[16 * 65];
    __shared__ float smax[16 * 65];
    __shared__ float gv[2 * HID];
    __shared__ float hc[HID];
    __shared__ float lg[C_OUT];
    __shared__ float s_lse;

    int g = blockIdx.x;
    int t = threadIdx.x;

    if (t == 0) {
        int lo = 0, hi = N_NODES;
        while (lo < hi) { int m = (lo + hi) >> 1; if (batch[m] < g) lo = m + 1; else hi = m; }
        s_se[0] = lo;
        lo = 0; hi = N_NODES;
        while (lo < hi) { int m = (lo + hi) >> 1; if (batch[m] < g + 1) lo = m + 1; else hi = m; }
        s_se[1] = lo;
    }
    __syncthreads();
    int start = s_se[0], end = s_se[1];

    int r  = t >> 4;
    int j4 = t & 15;
    const uint2* h2p = (const uint2*)g_hh;
    float4 sum = make_float4(0.f, 0.f, 0.f, 0.f);
    float4 mx  = make_float4(-INFINITY, -INFINITY, -INFINITY, -INFINITY);
    for (int i = start + r; i < end; i += 16) {
        uint2 v = h2p[i * 16 + j4];
        float2 a = __half22float2(bits_h2(v.x));
        float2 b = __half22float2(bits_h2(v.y));
        sum.x += a.x; sum.y += a.y; sum.z += b.x; sum.w += b.y;
        mx.x = fmaxf(mx.x, a.x); mx.y = fmaxf(mx.y, a.y);
        mx.z = fmaxf(mx.z, b.x); mx.w = fmaxf(mx.w, b.y);
    }
    ssum[r * 65 + 4 * j4 + 0] = sum.x; ssum[r * 65 + 4 * j4 + 1] = sum.y;
    ssum[r * 65 + 4 * j4 + 2] = sum.z; ssum[r * 65 + 4 * j4 + 3] = sum.w;
    smax[r * 65 + 4 * j4 + 0] = mx.x;  smax[r * 65 + 4 * j4 + 1] = mx.y;
    smax[r * 65 + 4 * j4 + 2] = mx.z;  smax[r * 65 + 4 * j4 + 3] = mx.w;
    __syncthreads();

    if (t < HID) {
        float s = 0.f, m = -INFINITY;
        #pragma unroll
        for (int q = 0; q < 16; q++) {
            s += ssum[q * 65 + t];
            m = fmaxf(m, smax[q * 65 + t]);
        }
        gv[t]       = s / (float)(end - start);
        gv[HID + t] = m;
    }
    __syncthreads();

    if (t < HID) {
        float s = bc1[t];
        #pragma unroll 16
        for (int k = 0; k < 2 * HID; k++) s += gv[k] * Wc1[k * HID + t];
        hc[t] = fmaxf(s, 0.f);
    }
    __syncthreads();

    if (t < C_OUT) {
        float l = bc2[t];
        #pragma unroll 16
        for (int j = 0; j < HID; j++) l += hc[j] * Wc2[j * C_OUT + t];
        lg[t] = l;
    }
    __syncthreads();

    if (t == 0) {
        float m = -INFINITY;
        #pragma unroll
        for (int c = 0; c < C_OUT; c++) m = fmaxf(m, lg[c]);
        float se = 0.f;
        #pragma unroll
        for (int c = 0; c < C_OUT; c++) se += expf(lg[c] - m);
        s_lse = m + logf(se);
    }
    __syncthreads();
    if (t < C_OUT) out[g * C_OUT + t] = lg[t] - s_lse;
}

extern "C" void kernel_launch(void* const* d_in, const int* in_sizes, int n_in,
                              void* d_out, int out_size) {
    const float* x     = (const float*)d_in[0];
    const int*   ei    = (const int*)  d_in[1];
    const int*   batch = (const int*)  d_in[2];
    // d_in[3] = num_graphs (constant 128, unused)
    const float* W0    = (const float*)d_in[4];
    const float* Ws    = (const float*)d_in[5];
    const float* bs    = (const float*)d_in[6];
    const float* gamma = (const float*)d_in[7];
    const float* beta  = (const float*)d_in[8];
    const float* rmean = (const float*)d_in[9];
    const float* rvar  = (const float*)d_in[10];
    const float* Wc1   = (const float*)d_in[11];
    const float* bc1   = (const float*)d_in[12];
    const float* Wc2   = (const float*)d_in[13];
    const float* bc2   = (const float*)d_in[14];
    float* out = (float*)d_out;

    const int NB_N    = (N_NODES + 255) / 256;
    const int NB_E8   = (N_EDGES / 8 + 255) / 256;
    const int NB_L0   = (N_NODES * 16 + 255) / 256;
    const int NB_GAT  = N_NODES / 16;
    const int NB_GEMM = (N_NODES + 127) / 128;

    // zero-init counters via graph memset nodes
    void* p_ecnt = 0; void* p_tot = 0;
    cudaGetSymbolAddress(&p_ecnt, g_ecnt);
    cudaGetSymbolAddress(&p_tot,  g_tot);
    cudaMemsetAsync(p_ecnt, 0, N_NODES * sizeof(int));
    cudaMemsetAsync(p_tot,  0, sizeof(int));

    // CSR build
    k_deg <<<NB_E8, 256>>>(ei);
    k_base<<<NB_N, 256>>>();
    k_fill<<<NB_E8, 256>>>(ei);

    // layer 0
    k_lin0  <<<NB_L0, 256>>>(x, W0);
    k_gather<<<NB_GAT, 256>>>(bs + 0 * HID, gamma + 0 * HID, beta + 0 * HID,
                              rmean + 0 * HID, rvar + 0 * HID, 1);
    // layer 1
    k_linh  <<<NB_GEMM, 256>>>(Ws + 0 * HID * HID);
    k_gather<<<NB_GAT, 256>>>(bs + 1 * HID, gamma + 1 * HID, beta + 1 * HID,
                              rmean + 1 * HID, rvar + 1 * HID, 1);
    // layer 2 (no relu)
    k_linh  <<<NB_GEMM, 256>>>(Ws + 1 * HID * HID);
    k_gather<<<NB_GAT, 256>>>(bs + 2 * HID, gamma + 2 * HID, beta + 2 * HID,
                              rmean + 2 * HID, rvar + 2 * HID, 0);

    // fused pooling + classifier
    k_poolcls<<<G_NUM, 256>>>(batch, Wc1, bc1, Wc2, bc2, out);
}

// round 10
// speedup vs baseline: 1.0771x; 1.0771x over previous
#include <cuda_runtime.h>
#include <cuda_fp16.h>
#include <math.h>

#define N_NODES 100000
#define N_EDGES 1200000
#define COL_CAP (N_EDGES + 3 * N_NODES + 16)
#define HID 64
#define G_NUM 128
#define C_OUT 10
#define D_IN 3
#define EPS_BN 1e-5f

static __device__ __forceinline__ unsigned int h2_bits(__half2 h) {
    return *reinterpret_cast<unsigned int*>(&h);
}
static __device__ __forceinline__ __half2 bits_h2(unsigned int u) {
    return *reinterpret_cast<__half2*>(&u);
}

// -------- scratch (static device globals; no runtime allocation) --------
__device__ int   g_ecnt[N_NODES];
__device__ int   g_base[N_NODES];     // after k_base: aligned start; after k_fill: start+cnt
__device__ __align__(16) int g_col[COL_CAP];
__device__ int   g_tot;
__device__ float g_dinv[N_NODES];
__device__ __align__(16) __half g_xwh[N_NODES * HID];   // (h@W)*dinv, fp16
__device__ __align__(16) float  g_h  [N_NODES * HID];   // layer output, fp32

// -------- in-degree over real edges (4 edges/thread via int4) --------
__global__ void __launch_bounds__(256) k_deg(const int* __restrict__ ei) {
    int idx = blockIdx.x * blockDim.x + threadIdx.x;           // < E/4
    if (idx >= N_EDGES / 4) return;
    int4 d = ((const int4*)(ei + N_EDGES))[idx];
    atomicAdd(&g_ecnt[d.x], 1);
    atomicAdd(&g_ecnt[d.y], 1);
    atomicAdd(&g_ecnt[d.z], 1);
    atomicAdd(&g_ecnt[d.w], 1);
}

// -------- dinv + CSR bases, 4-aligned allocations (warp scan + atomic) --------
__global__ void k_base() {
    int i = blockIdx.x * blockDim.x + threadIdx.x;
    int lane = threadIdx.x & 31;
    int c = (i < N_NODES) ? g_ecnt[i] : 0;
    if (i < N_NODES) g_dinv[i] = rsqrtf((float)(c + 1));
    int alloc = (c + 3) & ~3;          // pad to multiple of 4 -> 16B-aligned segments
    int incl = alloc;
    #pragma unroll
    for (int off = 1; off < 32; off <<= 1) {
        int v = __shfl_up_sync(0xffffffffu, incl, off);
        if (lane >= off) incl += v;
    }
    int excl = incl - alloc;
    int wsum = __shfl_sync(0xffffffffu, incl, 31);
    int wbase = 0;
    if (lane == 31) wbase = atomicAdd(&g_tot, wsum);
    wbase = __shfl_sync(0xffffffffu, wbase, 31);
    if (i < N_NODES) g_base[i] = wbase + excl;
}

// -------- CSR fill: cursor IS g_base (ends at start+cnt); 2 edges/thread ------
__global__ void __launch_bounds__(256) k_fill(const int* __restrict__ ei) {
    int idx = blockIdx.x * blockDim.x + threadIdx.x;           // < E/2
    if (idx >= N_EDGES / 2) return;
    int2 s = ((const int2*)ei)[idx];
    int2 d = ((const int2*)(ei + N_EDGES))[idx];
    int p0 = atomicAdd(&g_base[d.x], 1); g_col[p0] = s.x;
    int p1 = atomicAdd(&g_base[d.y], 1); g_col[p1] = s.y;
}

// -------- layer 0 linear: x[N,3] @ W0[3,64] * dinv -> fp16, 4 cols/thread -----
__global__ void __launch_bounds__(256) k_lin0(const float* __restrict__ x,
                                              const float* __restrict__ W0) {
    __shared__ float sW[D_IN * HID];
    int t = threadIdx.x;
    if (t < D_IN * HID) sW[t] = W0[t];
    __syncthreads();
    int idx = blockIdx.x * blockDim.x + t;                     // < N*16
    if (idx >= N_NODES * 16) return;
    int i = idx >> 4, j4 = idx & 15;
    float x0 = x[i * 3 + 0], x1 = x[i * 3 + 1], x2 = x[i * 3 + 2];
    float d = g_dinv[i];
    float o[4];
    #pragma unroll
    for (int q = 0; q < 4; q++) {
        int j = 4 * j4 + q;
        o[q] = (x0 * sW[j] + x1 * sW[64 + j] + x2 * sW[128 + j]) * d;
    }
    uint2 pk;
    pk.x = h2_bits(__floats2half2_rn(o[0], o[1]));
    pk.y = h2_bits(__floats2half2_rn(o[2], o[3]));
    ((uint2*)g_xwh)[idx] = pk;
}

// -------- hidden linear: register-tiled GEMM, 64x64/block, fp16 output -------
__global__ void __launch_bounds__(256) k_linh(const float* __restrict__ W) {
    __shared__ float sW [HID * HID];   // k-major: sW[k*64 + j]
    __shared__ float shT[HID * HID];   // transposed: shT[k*64 + node]
    int t = threadIdx.x;
    int node0 = blockIdx.x * 64;

    for (int q = t; q < 1024; q += 256)
        ((float4*)sW)[q] = ((const float4*)W)[q];

    int ln = t & 63;
    int c0 = t >> 6;
    #pragma unroll
    for (int cc = c0; cc < 16; cc += 4) {
        int gi = node0 + ln;
        float4 v = make_float4(0.f, 0.f, 0.f, 0.f);
        if (gi < N_NODES) v = ((const float4*)g_h)[gi * 16 + cc];
        shT[(4 * cc + 0) * 64 + ln] = v.x;
        shT[(4 * cc + 1) * 64 + ln] = v.y;
        shT[(4 * cc + 2) * 64 + ln] = v.z;
        shT[(4 * cc + 3) * 64 + ln] = v.w;
    }
    __syncthreads();

    int a = t >> 4;
    int b = t & 15;
    float4 acc0 = make_float4(0.f, 0.f, 0.f, 0.f);
    float4 acc1 = acc0, acc2 = acc0, acc3 = acc0;

    #pragma unroll 8
    for (int k = 0; k < 64; k++) {
        float4 vN = *(const float4*)&shT[k * 64 + 4 * a];
        float4 vW = *(const float4*)&sW [k * 64 + 4 * b];
        acc0.x += vN.x * vW.x; acc0.y += vN.x * vW.y; acc0.z += vN.x * vW.z; acc0.w += vN.x * vW.w;
        acc1.x += vN.y * vW.x; acc1.y += vN.y * vW.y; acc1.z += vN.y * vW.z; acc1.w += vN.y * vW.w;
        acc2.x += vN.z * vW.x; acc2.y += vN.z * vW.y; acc2.z += vN.z * vW.z; acc2.w += vN.z * vW.w;
        acc3.x += vN.w * vW.x; acc3.y += vN.w * vW.y; acc3.z += vN.w * vW.z; acc3.w += vN.w * vW.w;
    }

    float4 accs[4] = {acc0, acc1, acc2, acc3};
    #pragma unroll
    for (int r = 0; r < 4; r++) {
        int i = node0 + 4 * a + r;
        if (i < N_NODES) {
            float d = g_dinv[i];
            float4 o = accs[r];
            uint2 pk;
            pk.x = h2_bits(__floats2half2_rn(o.x * d, o.y * d));
            pk.y = h2_bits(__floats2half2_rn(o.z * d, o.w * d));
            ((uint2*)g_xwh)[i * 16 + b] = pk;
        }
    }
}

// -------- CSR gather: 8 edges in flight + half2 tree + fused BN epilogue ------
__global__ void __launch_bounds__(256) k_gather(const float* __restrict__ bb,
                                                const float* __restrict__ gamma,
                                                const float* __restrict__ beta,
                                                const float* __restrict__ mean,
                                                const float* __restrict__ var, int relu) {
    int t = threadIdx.x;
    int node = blockIdx.x * 16 + (t >> 4);   // N divisible by 16
    int j4 = t & 15;
    const uint2* xw2 = (const uint2*)g_xwh;

    int cnt  = g_ecnt[node];
    int base = g_base[node] - cnt;           // start (4-aligned)

    uint2 self = xw2[node * 16 + j4];
    float2 slo = __half22float2(bits_h2(self.x));
    float2 shi = __half22float2(bits_h2(self.y));
    float4 acc = make_float4(slo.x, slo.y, shi.x, shi.y);

    const int4* c4p = (const int4*)(g_col + base);   // 16B-aligned
    int k = 0;
    // 8 edges in flight: 2 col int4 loads + 8 row loads before any use
    for (; k + 8 <= cnt; k += 8) {
        int4 ca = __ldg(&c4p[(k >> 2) + 0]);
        int4 cb = __ldg(&c4p[(k >> 2) + 1]);
        uint2 r0 = __ldg(&xw2[ca.x * 16 + j4]);
        uint2 r1 = __ldg(&xw2[ca.y * 16 + j4]);
        uint2 r2 = __ldg(&xw2[ca.z * 16 + j4]);
        uint2 r3 = __ldg(&xw2[ca.w * 16 + j4]);
        uint2 r4 = __ldg(&xw2[cb.x * 16 + j4]);
        uint2 r5 = __ldg(&xw2[cb.y * 16 + j4]);
        uint2 r6 = __ldg(&xw2[cb.z * 16 + j4]);
        uint2 r7 = __ldg(&xw2[cb.w * 16 + j4]);
        __half2 lo = __hadd2(__hadd2(__hadd2(bits_h2(r0.x), bits_h2(r1.x)),
                                     __hadd2(bits_h2(r2.x), bits_h2(r3.x))),
                             __hadd2(__hadd2(bits_h2(r4.x), bits_h2(r5.x)),
                                     __hadd2(bits_h2(r6.x), bits_h2(r7.x))));
        __half2 hi = __hadd2(__hadd2(__hadd2(bits_h2(r0.y), bits_h2(r1.y)),
                                     __hadd2(bits_h2(r2.y), bits_h2(r3.y))),
                             __hadd2(__hadd2(bits_h2(r4.y), bits_h2(r5.y)),
                                     __hadd2(bits_h2(r6.y), bits_h2(r7.y))));
        float2 flo = __half22float2(lo);
        float2 fhi = __half22float2(hi);
        acc.x += flo.x; acc.y += flo.y; acc.z += fhi.x; acc.w += fhi.y;
    }
    for (; k + 4 <= cnt; k += 4) {
        int4 c4 = __ldg(&c4p[k >> 2]);
        uint2 r0 = __ldg(&xw2[c4.x * 16 + j4]);
        uint2 r1 = __ldg(&xw2[c4.y * 16 + j4]);
        uint2 r2 = __ldg(&xw2[c4.z * 16 + j4]);
        uint2 r3 = __ldg(&xw2[c4.w * 16 + j4]);
        __half2 lo = __hadd2(__hadd2(bits_h2(r0.x), bits_h2(r1.x)),
                             __hadd2(bits_h2(r2.x), bits_h2(r3.x)));
        __half2 hi = __hadd2(__hadd2(bits_h2(r0.y), bits_h2(r1.y)),
                             __hadd2(bits_h2(r2.y), bits_h2(r3.y)));
        float2 flo = __half22float2(lo);
        float2 fhi = __half22float2(hi);
        acc.x += flo.x; acc.y += flo.y; acc.z += fhi.x; acc.w += fhi.y;
    }
    for (; k < cnt; k++) {
        int s = __ldg(&g_col[base + k]);
        uint2 r = __ldg(&xw2[s * 16 + j4]);
        float2 a = __half22float2(bits_h2(r.x));
        float2 b = __half22float2(bits_h2(r.y));
        acc.x += a.x; acc.y += a.y; acc.z += b.x; acc.w += b.y;
    }

    float d = g_dinv[node];
    float4 vb  = ((const float4*)bb)[j4];
    float4 vg  = ((const float4*)gamma)[j4];
    float4 vbt = ((const float4*)beta)[j4];
    float4 vm  = ((const float4*)mean)[j4];
    float4 vv  = ((const float4*)var)[j4];
    float4 o;
    o.x = (acc.x * d + vb.x - vm.x) * (vg.x * rsqrtf(vv.x + EPS_BN)) + vbt.x;
    o.y = (acc.y * d + vb.y - vm.y) * (vg.y * rsqrtf(vv.y + EPS_BN)) + vbt.y;
    o.z = (acc.z * d + vb.z - vm.z) * (vg.z * rsqrtf(vv.z + EPS_BN)) + vbt.z;
    o.w = (acc.w * d + vb.w - vm.w) * (vg.w * rsqrtf(vv.w + EPS_BN)) + vbt.w;
    if (relu) {
        o.x = fmaxf(o.x, 0.f); o.y = fmaxf(o.y, 0.f);
        o.z = fmaxf(o.z, 0.f); o.w = fmaxf(o.w, 0.f);
    }
    ((float4*)g_h)[node * 16 + j4] = o;
}

// -------- fused pooling + classifier + log_softmax: 1 block / graph -----------
__global__ void __launch_bounds__(256) k_poolcls(const int* __restrict__ batch,
                                                 const float* __restrict__ Wc1,
                                                 const float* __restrict__ bc1,
                                                 const float* __restrict__ Wc2,
                                                 const float* __restrict__ bc2,
                                                 float* __restrict__ out) {
    __shared__ int s_se[2];
    __shared__ float ssum[16 * 65];
    __shared__ float smax[16 * 65];
    __shared__ float gv[2 * HID];
    __shared__ float hc[HID];
    __shared__ float lg[C_OUT];
    __shared__ float s_lse;

    int g = blockIdx.x;
    int t = threadIdx.x;

    if (t == 0) {
        int lo = 0, hi = N_NODES;
        while (lo < hi) { int m = (lo + hi) >> 1; if (batch[m] < g) lo = m + 1; else hi = m; }
        s_se[0] = lo;
        lo = 0; hi = N_NODES;
        while (lo < hi) { int m = (lo + hi) >> 1; if (batch[m] < g + 1) lo = m + 1; else hi = m; }
        s_se[1] = lo;
    }
    __syncthreads();
    int start = s_se[0], end = s_se[1];

    int r  = t >> 4;
    int j4 = t & 15;
    const float4* h4 = (const float4*)g_h;
    float4 sum = make_float4(0.f, 0.f, 0.f, 0.f);
    float4 mx  = make_float4(-INFINITY, -INFINITY, -INFINITY, -INFINITY);
    for (int i = start + r; i < end; i += 16) {
        float4 v = h4[i * 16 + j4];
        sum.x += v.x; sum.y += v.y; sum.z += v.z; sum.w += v.w;
        mx.x = fmaxf(mx.x, v.x); mx.y = fmaxf(mx.y, v.y);
        mx.z = fmaxf(mx.z, v.z); mx.w = fmaxf(mx.w, v.w);
    }
    ssum[r * 65 + 4 * j4 + 0] = sum.x; ssum[r * 65 + 4 * j4 + 1] = sum.y;
    ssum[r * 65 + 4 * j4 + 2] = sum.z; ssum[r * 65 + 4 * j4 + 3] = sum.w;
    smax[r * 65 + 4 * j4 + 0] = mx.x;  smax[r * 65 + 4 * j4 + 1] = mx.y;
    smax[r * 65 + 4 * j4 + 2] = mx.z;  smax[r * 65 + 4 * j4 + 3] = mx.w;
    __syncthreads();

    if (t < HID) {
        float s = 0.f, m = -INFINITY;
        #pragma unroll
        for (int q = 0; q < 16; q++) {
            s += ssum[q * 65 + t];
            m = fmaxf(m, smax[q * 65 + t]);
        }
        gv[t]       = s / (float)(end - start);
        gv[HID + t] = m;
    }
    __syncthreads();

    if (t < HID) {
        float s = bc1[t];
        #pragma unroll 16
        for (int k = 0; k < 2 * HID; k++) s += gv[k] * Wc1[k * HID + t];
        hc[t] = fmaxf(s, 0.f);
    }
    __syncthreads();

    if (t < C_OUT) {
        float l = bc2[t];
        #pragma unroll 16
        for (int j = 0; j < HID; j++) l += hc[j] * Wc2[j * C_OUT + t];
        lg[t] = l;
    }
    __syncthreads();

    if (t == 0) {
        float m = -INFINITY;
        #pragma unroll
        for (int c = 0; c < C_OUT; c++) m = fmaxf(m, lg[c]);
        float se = 0.f;
        #pragma unroll
        for (int c = 0; c < C_OUT; c++) se += expf(lg[c] - m);
        s_lse = m + logf(se);
    }
    __syncthreads();
    if (t < C_OUT) out[g * C_OUT + t] = lg[t] - s_lse;
}

extern "C" void kernel_launch(void* const* d_in, const int* in_sizes, int n_in,
                              void* d_out, int out_size) {
    const float* x     = (const float*)d_in[0];
    const int*   ei    = (const int*)  d_in[1];
    const int*   batch = (const int*)  d_in[2];
    // d_in[3] = num_graphs (constant 128, unused)
    const float* W0    = (const float*)d_in[4];
    const float* Ws    = (const float*)d_in[5];
    const float* bs    = (const float*)d_in[6];
    const float* gamma = (const float*)d_in[7];
    const float* beta  = (const float*)d_in[8];
    const float* rmean = (const float*)d_in[9];
    const float* rvar  = (const float*)d_in[10];
    const float* Wc1   = (const float*)d_in[11];
    const float* bc1   = (const float*)d_in[12];
    const float* Wc2   = (const float*)d_in[13];
    const float* bc2   = (const float*)d_in[14];
    float* out = (float*)d_out;

    const int NB_N    = (N_NODES + 255) / 256;
    const int NB_E4   = (N_EDGES / 4 + 255) / 256;
    const int NB_E2   = (N_EDGES / 2 + 255) / 256;
    const int NB_L0   = (N_NODES * 16 + 255) / 256;
    const int NB_GAT  = N_NODES / 16;
    const int NB_GEMM = (N_NODES + 63) / 64;

    // zero-init counters via graph memset nodes
    void* p_ecnt = 0; void* p_tot = 0;
    cudaGetSymbolAddress(&p_ecnt, g_ecnt);
    cudaGetSymbolAddress(&p_tot,  g_tot);
    cudaMemsetAsync(p_ecnt, 0, N_NODES * sizeof(int));
    cudaMemsetAsync(p_tot,  0, sizeof(int));

    // CSR build
    k_deg <<<NB_E4, 256>>>(ei);
    k_base<<<NB_N, 256>>>();
    k_fill<<<NB_E2, 256>>>(ei);

    // layer 0
    k_lin0  <<<NB_L0, 256>>>(x, W0);
    k_gather<<<NB_GAT, 256>>>(bs + 0 * HID, gamma + 0 * HID, beta + 0 * HID,
                              rmean + 0 * HID, rvar + 0 * HID, 1);
    // layer 1
    k_linh  <<<NB_GEMM, 256>>>(Ws + 0 * HID * HID);
    k_gather<<<NB_GAT, 256>>>(bs + 1 * HID, gamma + 1 * HID, beta + 1 * HID,
                              rmean + 1 * HID, rvar + 1 * HID, 1);
    // layer 2 (no relu)
    k_linh  <<<NB_GEMM, 256>>>(Ws + 1 * HID * HID);
    k_gather<<<NB_GAT, 256>>>(bs + 2 * HID, gamma + 2 * HID, beta + 2 * HID,
                              rmean + 2 * HID, rvar + 2 * HID, 0);

    // fused pooling + classifier
    k_poolcls<<<G_NUM, 256>>>(batch, Wc1, bc1, Wc2, bc2, out);
}

// round 11
// speedup vs baseline: 1.0775x; 1.0003x over previous
#include <cuda_runtime.h>
#include <cuda_fp16.h>
#include <math.h>

#define N_NODES 100000
#define N_EDGES 1200000
#define COL_CAP (N_EDGES + 3 * N_NODES + 16)
#define HID 64
#define G_NUM 128
#define C_OUT 10
#define D_IN 3
#define EPS_BN 1e-5f

static __device__ __forceinline__ unsigned int h2_bits(__half2 h) {
    return *reinterpret_cast<unsigned int*>(&h);
}
static __device__ __forceinline__ __half2 bits_h2(unsigned int u) {
    return *reinterpret_cast<__half2*>(&u);
}

// -------- scratch (static device globals; no runtime allocation) --------
__device__ int   g_ecnt[N_NODES];
__device__ int   g_base[N_NODES];     // after k_base: aligned start; after fill: start+cnt
__device__ __align__(16) int g_col[COL_CAP];
__device__ int   g_tot;
__device__ __align__(16) __half g_xwh[N_NODES * HID];   // (h@W)*dinv, fp16
__device__ __align__(16) float  g_h  [N_NODES * HID];   // layer output, fp32

// -------- in-degree over real edges (4 edges/thread via int4) --------
__global__ void __launch_bounds__(256) k_deg(const int* __restrict__ ei) {
    int idx = blockIdx.x * blockDim.x + threadIdx.x;           // < E/4
    if (idx >= N_EDGES / 4) return;
    int4 d = ((const int4*)(ei + N_EDGES))[idx];
    atomicAdd(&g_ecnt[d.x], 1);
    atomicAdd(&g_ecnt[d.y], 1);
    atomicAdd(&g_ecnt[d.z], 1);
    atomicAdd(&g_ecnt[d.w], 1);
}

// -------- CSR bases, 4-aligned allocations (warp scan + atomic) --------
__global__ void k_base() {
    int i = blockIdx.x * blockDim.x + threadIdx.x;
    int lane = threadIdx.x & 31;
    int c = (i < N_NODES) ? g_ecnt[i] : 0;
    int alloc = (c + 3) & ~3;          // pad to multiple of 4 -> 16B-aligned segments
    int incl = alloc;
    #pragma unroll
    for (int off = 1; off < 32; off <<= 1) {
        int v = __shfl_up_sync(0xffffffffu, incl, off);
        if (lane >= off) incl += v;
    }
    int excl = incl - alloc;
    int wsum = __shfl_sync(0xffffffffu, incl, 31);
    int wbase = 0;
    if (lane == 31) wbase = atomicAdd(&g_tot, wsum);
    wbase = __shfl_sync(0xffffffffu, wbase, 31);
    if (i < N_NODES) g_base[i] = wbase + excl;
}

// -------- merged: CSR fill (blocks [0,NB_FILL)) + layer-0 linear (rest) -------
// Both depend only on k_base; run concurrently in one launch.
#define NB_FILL ((N_EDGES / 2 + 255) / 256)
#define NB_L0   ((N_NODES * 16 + 255) / 256)
__global__ void __launch_bounds__(256) k_fill_lin0(const int* __restrict__ ei,
                                                   const float* __restrict__ x,
                                                   const float* __restrict__ W0) {
    if (blockIdx.x < NB_FILL) {
        // ---- CSR fill: cursor IS g_base; 2 edges/thread ----
        int idx = blockIdx.x * blockDim.x + threadIdx.x;       // < E/2
        if (idx >= N_EDGES / 2) return;
        int2 s = ((const int2*)ei)[idx];
        int2 d = ((const int2*)(ei + N_EDGES))[idx];
        int p0 = atomicAdd(&g_base[d.x], 1); g_col[p0] = s.x;
        int p1 = atomicAdd(&g_base[d.y], 1); g_col[p1] = s.y;
    } else {
        // ---- layer 0: x[N,3] @ W0[3,64] * dinv -> fp16, 4 cols/thread ----
        __shared__ float sW[D_IN * HID];
        int t = threadIdx.x;
        if (t < D_IN * HID) sW[t] = W0[t];
        __syncthreads();
        int idx = (blockIdx.x - NB_FILL) * blockDim.x + t;     // < N*16
        if (idx >= N_NODES * 16) return;
        int i = idx >> 4, j4 = idx & 15;
        float x0 = x[i * 3 + 0], x1 = x[i * 3 + 1], x2 = x[i * 3 + 2];
        float d = rsqrtf((float)(g_ecnt[i] + 1));
        float o[4];
        #pragma unroll
        for (int q = 0; q < 4; q++) {
            int j = 4 * j4 + q;
            o[q] = (x0 * sW[j] + x1 * sW[64 + j] + x2 * sW[128 + j]) * d;
        }
        uint2 pk;
        pk.x = h2_bits(__floats2half2_rn(o[0], o[1]));
        pk.y = h2_bits(__floats2half2_rn(o[2], o[3]));
        ((uint2*)g_xwh)[idx] = pk;
    }
}

// -------- hidden linear: register-tiled GEMM, 64x64/block, fp16 output -------
__global__ void __launch_bounds__(256) k_linh(const float* __restrict__ W) {
    __shared__ float sW [HID * HID];   // k-major: sW[k*64 + j]
    __shared__ float shT[HID * HID];   // transposed: shT[k*64 + node]
    int t = threadIdx.x;
    int node0 = blockIdx.x * 64;

    for (int q = t; q < 1024; q += 256)
        ((float4*)sW)[q] = ((const float4*)W)[q];

    int ln = t & 63;
    int c0 = t >> 6;
    #pragma unroll
    for (int cc = c0; cc < 16; cc += 4) {
        int gi = node0 + ln;
        float4 v = make_float4(0.f, 0.f, 0.f, 0.f);
        if (gi < N_NODES) v = ((const float4*)g_h)[gi * 16 + cc];
        shT[(4 * cc + 0) * 64 + ln] = v.x;
        shT[(4 * cc + 1) * 64 + ln] = v.y;
        shT[(4 * cc + 2) * 64 + ln] = v.z;
        shT[(4 * cc + 3) * 64 + ln] = v.w;
    }
    __syncthreads();

    int a = t >> 4;
    int b = t & 15;
    float4 acc0 = make_float4(0.f, 0.f, 0.f, 0.f);
    float4 acc1 = acc0, acc2 = acc0, acc3 = acc0;

    #pragma unroll 8
    for (int k = 0; k < 64; k++) {
        float4 vN = *(const float4*)&shT[k * 64 + 4 * a];
        float4 vW = *(const float4*)&sW [k * 64 + 4 * b];
        acc0.x += vN.x * vW.x; acc0.y += vN.x * vW.y; acc0.z += vN.x * vW.z; acc0.w += vN.x * vW.w;
        acc1.x += vN.y * vW.x; acc1.y += vN.y * vW.y; acc1.z += vN.y * vW.z; acc1.w += vN.y * vW.w;
        acc2.x += vN.z * vW.x; acc2.y += vN.z * vW.y; acc2.z += vN.z * vW.z; acc2.w += vN.z * vW.w;
        acc3.x += vN.w * vW.x; acc3.y += vN.w * vW.y; acc3.z += vN.w * vW.z; acc3.w += vN.w * vW.w;
    }

    float4 accs[4] = {acc0, acc1, acc2, acc3};
    #pragma unroll
    for (int r = 0; r < 4; r++) {
        int i = node0 + 4 * a + r;
        if (i < N_NODES) {
            float d = rsqrtf((float)(g_ecnt[i] + 1));
            float4 o = accs[r];
            uint2 pk;
            pk.x = h2_bits(__floats2half2_rn(o.x * d, o.y * d));
            pk.y = h2_bits(__floats2half2_rn(o.z * d, o.w * d));
            ((uint2*)g_xwh)[i * 16 + b] = pk;
        }
    }
}

// -------- CSR gather: 8 edges in flight + half2 tree + fused BN epilogue ------
__global__ void __launch_bounds__(256) k_gather(const float* __restrict__ bb,
                                                const float* __restrict__ gamma,
                                                const float* __restrict__ beta,
                                                const float* __restrict__ mean,
                                                const float* __restrict__ var, int relu) {
    int t = threadIdx.x;
    int node = blockIdx.x * 16 + (t >> 4);   // N divisible by 16
    int j4 = t & 15;
    const uint2* xw2 = (const uint2*)g_xwh;

    int cnt  = g_ecnt[node];
    int base = g_base[node] - cnt;           // start (4-aligned)

    uint2 self = xw2[node * 16 + j4];
    float2 slo = __half22float2(bits_h2(self.x));
    float2 shi = __half22float2(bits_h2(self.y));
    float4 acc = make_float4(slo.x, slo.y, shi.x, shi.y);

    const int4* c4p = (const int4*)(g_col + base);   // 16B-aligned
    int k = 0;
    for (; k + 8 <= cnt; k += 8) {
        int4 ca = __ldg(&c4p[(k >> 2) + 0]);
        int4 cb = __ldg(&c4p[(k >> 2) + 1]);
        uint2 r0 = __ldg(&xw2[ca.x * 16 + j4]);
        uint2 r1 = __ldg(&xw2[ca.y * 16 + j4]);
        uint2 r2 = __ldg(&xw2[ca.z * 16 + j4]);
        uint2 r3 = __ldg(&xw2[ca.w * 16 + j4]);
        uint2 r4 = __ldg(&xw2[cb.x * 16 + j4]);
        uint2 r5 = __ldg(&xw2[cb.y * 16 + j4]);
        uint2 r6 = __ldg(&xw2[cb.z * 16 + j4]);
        uint2 r7 = __ldg(&xw2[cb.w * 16 + j4]);
        __half2 lo = __hadd2(__hadd2(__hadd2(bits_h2(r0.x), bits_h2(r1.x)),
                                     __hadd2(bits_h2(r2.x), bits_h2(r3.x))),
                             __hadd2(__hadd2(bits_h2(r4.x), bits_h2(r5.x)),
                                     __hadd2(bits_h2(r6.x), bits_h2(r7.x))));
        __half2 hi = __hadd2(__hadd2(__hadd2(bits_h2(r0.y), bits_h2(r1.y)),
                                     __hadd2(bits_h2(r2.y), bits_h2(r3.y))),
                             __hadd2(__hadd2(bits_h2(r4.y), bits_h2(r5.y)),
                                     __hadd2(bits_h2(r6.y), bits_h2(r7.y))));
        float2 flo = __half22float2(lo);
        float2 fhi = __half22float2(hi);
        acc.x += flo.x; acc.y += flo.y; acc.z += fhi.x; acc.w += fhi.y;
    }
    for (; k + 4 <= cnt; k += 4) {
        int4 c4 = __ldg(&c4p[k >> 2]);
        uint2 r0 = __ldg(&xw2[c4.x * 16 + j4]);
        uint2 r1 = __ldg(&xw2[c4.y * 16 + j4]);
        uint2 r2 = __ldg(&xw2[c4.z * 16 + j4]);
        uint2 r3 = __ldg(&xw2[c4.w * 16 + j4]);
        __half2 lo = __hadd2(__hadd2(bits_h2(r0.x), bits_h2(r1.x)),
                             __hadd2(bits_h2(r2.x), bits_h2(r3.x)));
        __half2 hi = __hadd2(__hadd2(bits_h2(r0.y), bits_h2(r1.y)),
                             __hadd2(bits_h2(r2.y), bits_h2(r3.y)));
        float2 flo = __half22float2(lo);
        float2 fhi = __half22float2(hi);
        acc.x += flo.x; acc.y += flo.y; acc.z += fhi.x; acc.w += fhi.y;
    }
    for (; k < cnt; k++) {
        int s = __ldg(&g_col[base + k]);
        uint2 r = __ldg(&xw2[s * 16 + j4]);
        float2 a = __half22float2(bits_h2(r.x));
        float2 b = __half22float2(bits_h2(r.y));
        acc.x += a.x; acc.y += a.y; acc.z += b.x; acc.w += b.y;
    }

    float d = rsqrtf((float)(cnt + 1));
    float4 vb  = ((const float4*)bb)[j4];
    float4 vg  = ((const float4*)gamma)[j4];
    float4 vbt = ((const float4*)beta)[j4];
    float4 vm  = ((const float4*)mean)[j4];
    float4 vv  = ((const float4*)var)[j4];
    float4 o;
    o.x = (acc.x * d + vb.x - vm.x) * (vg.x * rsqrtf(vv.x + EPS_BN)) + vbt.x;
    o.y = (acc.y * d + vb.y - vm.y) * (vg.y * rsqrtf(vv.y + EPS_BN)) + vbt.y;
    o.z = (acc.z * d + vb.z - vm.z) * (vg.z * rsqrtf(vv.z + EPS_BN)) + vbt.z;
    o.w = (acc.w * d + vb.w - vm.w) * (vg.w * rsqrtf(vv.w + EPS_BN)) + vbt.w;
    if (relu) {
        o.x = fmaxf(o.x, 0.f); o.y = fmaxf(o.y, 0.f);
        o.z = fmaxf(o.z, 0.f); o.w = fmaxf(o.w, 0.f);
    }
    ((float4*)g_h)[node * 16 + j4] = o;
}

// -------- fused pooling + classifier + log_softmax: 1 block / graph -----------
__global__ void __launch_bounds__(256) k_poolcls(const int* __restrict__ batch,
                                                 const float* __restrict__ Wc1,
                                                 const float* __restrict__ bc1,
                                                 const float* __restrict__ Wc2,
                                                 const float* __restrict__ bc2,
                                                 float* __restrict__ out) {
    __shared__ int s_se[2];
    __shared__ float ssum[16 * 65];
    __shared__ float smax[16 * 65];
    __shared__ float gv[2 * HID];
    __shared__ float hc[HID];
    __shared__ float lg[C_OUT];
    __shared__ float s_lse;

    int g = blockIdx.x;
    int t = threadIdx.x;

    if (t == 0) {
        int lo = 0, hi = N_NODES;
        while (lo < hi) { int m = (lo + hi) >> 1; if (batch[m] < g) lo = m + 1; else hi = m; }
        s_se[0] = lo;
        lo = 0; hi = N_NODES;
        while (lo < hi) { int m = (lo + hi) >> 1; if (batch[m] < g + 1) lo = m + 1; else hi = m; }
        s_se[1] = lo;
    }
    __syncthreads();
    int start = s_se[0], end = s_se[1];

    int r  = t >> 4;
    int j4 = t & 15;
    const float4* h4 = (const float4*)g_h;
    float4 sum = make_float4(0.f, 0.f, 0.f, 0.f);
    float4 mx  = make_float4(-INFINITY, -INFINITY, -INFINITY, -INFINITY);
    for (int i = start + r; i < end; i += 16) {
        float4 v = h4[i * 16 + j4];
        sum.x += v.x; sum.y += v.y; sum.z += v.z; sum.w += v.w;
        mx.x = fmaxf(mx.x, v.x); mx.y = fmaxf(mx.y, v.y);
        mx.z = fmaxf(mx.z, v.z); mx.w = fmaxf(mx.w, v.w);
    }
    ssum[r * 65 + 4 * j4 + 0] = sum.x; ssum[r * 65 + 4 * j4 + 1] = sum.y;
    ssum[r * 65 + 4 * j4 + 2] = sum.z; ssum[r * 65 + 4 * j4 + 3] = sum.w;
    smax[r * 65 + 4 * j4 + 0] = mx.x;  smax[r * 65 + 4 * j4 + 1] = mx.y;
    smax[r * 65 + 4 * j4 + 2] = mx.z;  smax[r * 65 + 4 * j4 + 3] = mx.w;
    __syncthreads();

    if (t < HID) {
        float s = 0.f, m = -INFINITY;
        #pragma unroll
        for (int q = 0; q < 16; q++) {
            s += ssum[q * 65 + t];
            m = fmaxf(m, smax[q * 65 + t]);
        }
        gv[t]       = s / (float)(end - start);
        gv[HID + t] = m;
    }
    __syncthreads();

    if (t < HID) {
        float s = bc1[t];
        #pragma unroll 16
        for (int k = 0; k < 2 * HID; k++) s += gv[k] * Wc1[k * HID + t];
        hc[t] = fmaxf(s, 0.f);
    }
    __syncthreads();

    if (t < C_OUT) {
        float l = bc2[t];
        #pragma unroll 16
        for (int j = 0; j < HID; j++) l += hc[j] * Wc2[j * C_OUT + t];
        lg[t] = l;
    }
    __syncthreads();

    if (t == 0) {
        float m = -INFINITY;
        #pragma unroll
        for (int c = 0; c < C_OUT; c++) m = fmaxf(m, lg[c]);
        float se = 0.f;
        #pragma unroll
        for (int c = 0; c < C_OUT; c++) se += expf(lg[c] - m);
        s_lse = m + logf(se);
    }
    __syncthreads();
    if (t < C_OUT) out[g * C_OUT + t] = lg[t] - s_lse;
}

extern "C" void kernel_launch(void* const* d_in, const int* in_sizes, int n_in,
                              void* d_out, int out_size) {
    const float* x     = (const float*)d_in[0];
    const int*   ei    = (const int*)  d_in[1];
    const int*   batch = (const int*)  d_in[2];
    // d_in[3] = num_graphs (constant 128, unused)
    const float* W0    = (const float*)d_in[4];
    const float* Ws    = (const float*)d_in[5];
    const float* bs    = (const float*)d_in[6];
    const float* gamma = (const float*)d_in[7];
    const float* beta  = (const float*)d_in[8];
    const float* rmean = (const float*)d_in[9];
    const float* rvar  = (const float*)d_in[10];
    const float* Wc1   = (const float*)d_in[11];
    const float* bc1   = (const float*)d_in[12];
    const float* Wc2   = (const float*)d_in[13];
    const float* bc2   = (const float*)d_in[14];
    float* out = (float*)d_out;

    const int NB_N    = (N_NODES + 255) / 256;
    const int NB_E4   = (N_EDGES / 4 + 255) / 256;
    const int NB_GAT  = N_NODES / 16;
    const int NB_GEMM = (N_NODES + 63) / 64;

    // zero-init counters via graph memset nodes
    void* p_ecnt = 0; void* p_tot = 0;
    cudaGetSymbolAddress(&p_ecnt, g_ecnt);
    cudaGetSymbolAddress(&p_tot,  g_tot);
    cudaMemsetAsync(p_ecnt, 0, N_NODES * sizeof(int));
    cudaMemsetAsync(p_tot,  0, sizeof(int));

    // CSR build (fill overlapped with layer-0 linear in one launch)
    k_deg      <<<NB_E4, 256>>>(ei);
    k_base     <<<NB_N, 256>>>();
    k_fill_lin0<<<NB_FILL + NB_L0, 256>>>(ei, x, W0);

    // layer 0 aggregate
    k_gather<<<NB_GAT, 256>>>(bs + 0 * HID, gamma + 0 * HID, beta + 0 * HID,
                              rmean + 0 * HID, rvar + 0 * HID, 1);
    // layer 1
    k_linh  <<<NB_GEMM, 256>>>(Ws + 0 * HID * HID);
    k_gather<<<NB_GAT, 256>>>(bs + 1 * HID, gamma + 1 * HID, beta + 1 * HID,
                              rmean + 1 * HID, rvar + 1 * HID, 1);
    // layer 2 (no relu)
    k_linh  <<<NB_GEMM, 256>>>(Ws + 1 * HID * HID);
    k_gather<<<NB_GAT, 256>>>(bs + 2 * HID, gamma + 2 * HID, beta + 2 * HID,
                              rmean + 2 * HID, rvar + 2 * HID, 0);

    // fused pooling + classifier
    k_poolcls<<<G_NUM, 256>>>(batch, Wc1, bc1, Wc2, bc2, out);
}

// round 12
// speedup vs baseline: 1.0776x; 1.0002x over previous
#include <cuda_runtime.h>
#include <cuda_fp16.h>
#include <mma.h>
#include <math.h>

using namespace nvcuda;

#define N_NODES 100000
#define N_EDGES 1200000
#define COL_CAP (N_EDGES + 3 * N_NODES + 16)
#define HID 64
#define G_NUM 128
#define C_OUT 10
#define D_IN 3
#define EPS_BN 1e-5f

static __device__ __forceinline__ unsigned int h2_bits(__half2 h) {
    return *reinterpret_cast<unsigned int*>(&h);
}
static __device__ __forceinline__ __half2 bits_h2(unsigned int u) {
    return *reinterpret_cast<__half2*>(&u);
}

// -------- scratch (static device globals; no runtime allocation) --------
__device__ int   g_ecnt[N_NODES];
__device__ int   g_base[N_NODES];     // after k_base: aligned start; after fill: start+cnt
__device__ __align__(16) int g_col[COL_CAP];
__device__ int   g_tot;
__device__ __align__(16) __half g_xwh[N_NODES * HID];   // (h@W)*dinv, fp16
__device__ __align__(16) float  g_h  [N_NODES * HID];   // layer output, fp32

// -------- in-degree over real edges (4 edges/thread via int4) --------
__global__ void __launch_bounds__(256) k_deg(const int* __restrict__ ei) {
    int idx = blockIdx.x * blockDim.x + threadIdx.x;           // < E/4
    if (idx >= N_EDGES / 4) return;
    int4 d = ((const int4*)(ei + N_EDGES))[idx];
    atomicAdd(&g_ecnt[d.x], 1);
    atomicAdd(&g_ecnt[d.y], 1);
    atomicAdd(&g_ecnt[d.z], 1);
    atomicAdd(&g_ecnt[d.w], 1);
}

// -------- CSR bases, 4-aligned allocations (warp scan + atomic) --------
__global__ void k_base() {
    int i = blockIdx.x * blockDim.x + threadIdx.x;
    int lane = threadIdx.x & 31;
    int c = (i < N_NODES) ? g_ecnt[i] : 0;
    int alloc = (c + 3) & ~3;          // pad to multiple of 4 -> 16B-aligned segments
    int incl = alloc;
    #pragma unroll
    for (int off = 1; off < 32; off <<= 1) {
        int v = __shfl_up_sync(0xffffffffu, incl, off);
        if (lane >= off) incl += v;
    }
    int excl = incl - alloc;
    int wsum = __shfl_sync(0xffffffffu, incl, 31);
    int wbase = 0;
    if (lane == 31) wbase = atomicAdd(&g_tot, wsum);
    wbase = __shfl_sync(0xffffffffu, wbase, 31);
    if (i < N_NODES) g_base[i] = wbase + excl;
}

// -------- merged: CSR fill (blocks [0,NB_FILL)) + layer-0 linear (rest) -------
#define NB_FILL ((N_EDGES / 2 + 255) / 256)
#define NB_L0   ((N_NODES * 16 + 255) / 256)
__global__ void __launch_bounds__(256) k_fill_lin0(const int* __restrict__ ei,
                                                   const float* __restrict__ x,
                                                   const float* __restrict__ W0) {
    if (blockIdx.x < NB_FILL) {
        int idx = blockIdx.x * blockDim.x + threadIdx.x;       // < E/2
        if (idx >= N_EDGES / 2) return;
        int2 s = ((const int2*)ei)[idx];
        int2 d = ((const int2*)(ei + N_EDGES))[idx];
        int p0 = atomicAdd(&g_base[d.x], 1); g_col[p0] = s.x;
        int p1 = atomicAdd(&g_base[d.y], 1); g_col[p1] = s.y;
    } else {
        __shared__ float sW[D_IN * HID];
        int t = threadIdx.x;
        if (t < D_IN * HID) sW[t] = W0[t];
        __syncthreads();
        int idx = (blockIdx.x - NB_FILL) * blockDim.x + t;     // < N*16
        if (idx >= N_NODES * 16) return;
        int i = idx >> 4, j4 = idx & 15;
        float x0 = x[i * 3 + 0], x1 = x[i * 3 + 1], x2 = x[i * 3 + 2];
        float d = rsqrtf((float)(g_ecnt[i] + 1));
        float o[4];
        #pragma unroll
        for (int q = 0; q < 4; q++) {
            int j = 4 * j4 + q;
            o[q] = (x0 * sW[j] + x1 * sW[64 + j] + x2 * sW[128 + j]) * d;
        }
        uint2 pk;
        pk.x = h2_bits(__floats2half2_rn(o[0], o[1]));
        pk.y = h2_bits(__floats2half2_rn(o[2], o[3]));
        ((uint2*)g_xwh)[idx] = pk;
    }
}

// -------- hidden linear via WMMA: 128 nodes x 64 cols / block, 8 warps --------
// A = h[i](fp32->fp16)*dinv, B = W (fp32->fp16), fp32 accum -> fp16 g_xwh
__global__ void __launch_bounds__(256) k_linh(const float* __restrict__ W) {
    __shared__ __align__(16) char smem[32768];
    __half* sA = (__half*)smem;              // [128][64] fp16, 16KB
    __half* sB = (__half*)(smem + 16384);    // [64][64]  fp16,  8KB
    float*  sO = (float*)smem;               // [128][64] fp32, 32KB (reused)

    int t = threadIdx.x;
    int warp = t >> 5;
    int node0 = blockIdx.x * 128;

    // W fp32 -> sB fp16 (1024 float4)
    for (int q = t; q < 1024; q += 256) {
        float4 w = ((const float4*)W)[q];
        uint2 pk;
        pk.x = h2_bits(__floats2half2_rn(w.x, w.y));
        pk.y = h2_bits(__floats2half2_rn(w.z, w.w));
        ((uint2*)sB)[q] = pk;
    }
    // g_h fp32 * dinv -> sA fp16 (2048 float4 reads)
    for (int q = t; q < 2048; q += 256) {
        int r = q >> 4;
        int gi = node0 + r;
        uint2 pk = make_uint2(0u, 0u);
        if (gi < N_NODES) {
            float4 v = ((const float4*)g_h)[gi * 16 + (q & 15)];
            float d = rsqrtf((float)(g_ecnt[gi] + 1));
            pk.x = h2_bits(__floats2half2_rn(v.x * d, v.y * d));
            pk.y = h2_bits(__floats2half2_rn(v.z * d, v.w * d));
        }
        ((uint2*)sA)[q] = pk;
    }
    __syncthreads();

    // each warp: 16 rows x 64 cols
    wmma::fragment<wmma::accumulator, 16, 16, 16, float> fc[4];
    #pragma unroll
    for (int n = 0; n < 4; n++) wmma::fill_fragment(fc[n], 0.0f);

    #pragma unroll
    for (int k = 0; k < 4; k++) {
        wmma::fragment<wmma::matrix_a, 16, 16, 16, __half, wmma::row_major> fa;
        wmma::load_matrix_sync(fa, sA + (warp * 16) * HID + k * 16, HID);
        #pragma unroll
        for (int n = 0; n < 4; n++) {
            wmma::fragment<wmma::matrix_b, 16, 16, 16, __half, wmma::row_major> fb;
            wmma::load_matrix_sync(fb, sB + (k * 16) * HID + n * 16, HID);
            wmma::mma_sync(fc[n], fa, fb, fc[n]);
        }
    }
    __syncthreads();   // done with sA/sB; reuse as sO

    #pragma unroll
    for (int n = 0; n < 4; n++)
        wmma::store_matrix_sync(sO + (warp * 16) * HID + n * 16, fc[n], HID,
                                wmma::mem_row_major);
    __syncthreads();

    // pack sO fp32 -> g_xwh fp16
    for (int q = t; q < 2048; q += 256) {
        int r = q >> 4;
        int gi = node0 + r;
        if (gi < N_NODES) {
            float4 v = ((const float4*)sO)[q];
            uint2 pk;
            pk.x = h2_bits(__floats2half2_rn(v.x, v.y));
            pk.y = h2_bits(__floats2half2_rn(v.z, v.w));
            ((uint2*)g_xwh)[gi * 16 + (q & 15)] = pk;
        }
    }
}

// -------- CSR gather: 128-thread blocks, 8 edges in flight, fused BN ----------
__global__ void __launch_bounds__(128) k_gather(const float* __restrict__ bb,
                                                const float* __restrict__ gamma,
                                                const float* __restrict__ beta,
                                                const float* __restrict__ mean,
                                                const float* __restrict__ var, int relu) {
    int t = threadIdx.x;
    int node = blockIdx.x * 8 + (t >> 4);    // N divisible by 8
    int j4 = t & 15;
    const uint2* xw2 = (const uint2*)g_xwh;

    int cnt  = g_ecnt[node];
    int base = g_base[node] - cnt;           // start (4-aligned)

    uint2 self = xw2[node * 16 + j4];
    float2 slo = __half22float2(bits_h2(self.x));
    float2 shi = __half22float2(bits_h2(self.y));
    float4 acc = make_float4(slo.x, slo.y, shi.x, shi.y);

    const int4* c4p = (const int4*)(g_col + base);   // 16B-aligned
    int k = 0;
    for (; k + 8 <= cnt; k += 8) {
        int4 ca = __ldg(&c4p[(k >> 2) + 0]);
        int4 cb = __ldg(&c4p[(k >> 2) + 1]);
        uint2 r0 = __ldg(&xw2[ca.x * 16 + j4]);
        uint2 r1 = __ldg(&xw2[ca.y * 16 + j4]);
        uint2 r2 = __ldg(&xw2[ca.z * 16 + j4]);
        uint2 r3 = __ldg(&xw2[ca.w * 16 + j4]);
        uint2 r4 = __ldg(&xw2[cb.x * 16 + j4]);
        uint2 r5 = __ldg(&xw2[cb.y * 16 + j4]);
        uint2 r6 = __ldg(&xw2[cb.z * 16 + j4]);
        uint2 r7 = __ldg(&xw2[cb.w * 16 + j4]);
        __half2 lo = __hadd2(__hadd2(__hadd2(bits_h2(r0.x), bits_h2(r1.x)),
                                     __hadd2(bits_h2(r2.x), bits_h2(r3.x))),
                             __hadd2(__hadd2(bits_h2(r4.x), bits_h2(r5.x)),
                                     __hadd2(bits_h2(r6.x), bits_h2(r7.x))));
        __half2 hi = __hadd2(__hadd2(__hadd2(bits_h2(r0.y), bits_h2(r1.y)),
                                     __hadd2(bits_h2(r2.y), bits_h2(r3.y))),
                             __hadd2(__hadd2(bits_h2(r4.y), bits_h2(r5.y)),
                                     __hadd2(bits_h2(r6.y), bits_h2(r7.y))));
        float2 flo = __half22float2(lo);
        float2 fhi = __half22float2(hi);
        acc.x += flo.x; acc.y += flo.y; acc.z += fhi.x; acc.w += fhi.y;
    }
    for (; k + 4 <= cnt; k += 4) {
        int4 c4 = __ldg(&c4p[k >> 2]);
        uint2 r0 = __ldg(&xw2[c4.x * 16 + j4]);
        uint2 r1 = __ldg(&xw2[c4.y * 16 + j4]);
        uint2 r2 = __ldg(&xw2[c4.z * 16 + j4]);
        uint2 r3 = __ldg(&xw2[c4.w * 16 + j4]);
        __half2 lo = __hadd2(__hadd2(bits_h2(r0.x), bits_h2(r1.x)),
                             __hadd2(bits_h2(r2.x), bits_h2(r3.x)));
        __half2 hi = __hadd2(__hadd2(bits_h2(r0.y), bits_h2(r1.y)),
                             __hadd2(bits_h2(r2.y), bits_h2(r3.y)));
        float2 flo = __half22float2(lo);
        float2 fhi = __half22float2(hi);
        acc.x += flo.x; acc.y += flo.y; acc.z += fhi.x; acc.w += fhi.y;
    }
    for (; k < cnt; k++) {
        int s = __ldg(&g_col[base + k]);
        uint2 r = __ldg(&xw2[s * 16 + j4]);
        float2 a = __half22float2(bits_h2(r.x));
        float2 b = __half22float2(bits_h2(r.y));
        acc.x += a.x; acc.y += a.y; acc.z += b.x; acc.w += b.y;
    }

    float d = rsqrtf((float)(cnt + 1));
    float4 vb  = ((const float4*)bb)[j4];
    float4 vg  = ((const float4*)gamma)[j4];
    float4 vbt = ((const float4*)beta)[j4];
    float4 vm  = ((const float4*)mean)[j4];
    float4 vv  = ((const float4*)var)[j4];
    float4 o;
    o.x = (acc.x * d + vb.x - vm.x) * (vg.x * rsqrtf(vv.x + EPS_BN)) + vbt.x;
    o.y = (acc.y * d + vb.y - vm.y) * (vg.y * rsqrtf(vv.y + EPS_BN)) + vbt.y;
    o.z = (acc.z * d + vb.z - vm.z) * (vg.z * rsqrtf(vv.z + EPS_BN)) + vbt.z;
    o.w = (acc.w * d + vb.w - vm.w) * (vg.w * rsqrtf(vv.w + EPS_BN)) + vbt.w;
    if (relu) {
        o.x = fmaxf(o.x, 0.f); o.y = fmaxf(o.y, 0.f);
        o.z = fmaxf(o.z, 0.f); o.w = fmaxf(o.w, 0.f);
    }
    ((float4*)g_h)[node * 16 + j4] = o;
}

// -------- fused pooling + classifier + log_softmax: 1 block / graph -----------
__global__ void __launch_bounds__(256) k_poolcls(const int* __restrict__ batch,
                                                 const float* __restrict__ Wc1,
                                                 const float* __restrict__ bc1,
                                                 const float* __restrict__ Wc2,
                                                 const float* __restrict__ bc2,
                                                 float* __restrict__ out) {
    __shared__ int s_se[2];
    __shared__ float ssum[16 * 65];
    __shared__ float smax[16 * 65];
    __shared__ float gv[2 * HID];
    __shared__ float hc[HID];
    __shared__ float lg[C_OUT];
    __shared__ float s_lse;

    int g = blockIdx.x;
    int t = threadIdx.x;

    if (t == 0) {
        int lo = 0, hi = N_NODES;
        while (lo < hi) { int m = (lo + hi) >> 1; if (batch[m] < g) lo = m + 1; else hi = m; }
        s_se[0] = lo;
        lo = 0; hi = N_NODES;
        while (lo < hi) { int m = (lo + hi) >> 1; if (batch[m] < g + 1) lo = m + 1; else hi = m; }
        s_se[1] = lo;
    }
    __syncthreads();
    int start = s_se[0], end = s_se[1];

    int r  = t >> 4;
    int j4 = t & 15;
    const float4* h4 = (const float4*)g_h;
    float4 sum = make_float4(0.f, 0.f, 0.f, 0.f);
    float4 mx  = make_float4(-INFINITY, -INFINITY, -INFINITY, -INFINITY);
    for (int i = start + r; i < end; i += 16) {
        float4 v = h4[i * 16 + j4];
        sum.x += v.x; sum.y += v.y; sum.z += v.z; sum.w += v.w;
        mx.x = fmaxf(mx.x, v.x); mx.y = fmaxf(mx.y, v.y);
        mx.z = fmaxf(mx.z, v.z); mx.w = fmaxf(mx.w, v.w);
    }
    ssum[r * 65 + 4 * j4 + 0] = sum.x; ssum[r * 65 + 4 * j4 + 1] = sum.y;
    ssum[r * 65 + 4 * j4 + 2] = sum.z; ssum[r * 65 + 4 * j4 + 3] = sum.w;
    smax[r * 65 + 4 * j4 + 0] = mx.x;  smax[r * 65 + 4 * j4 + 1] = mx.y;
    smax[r * 65 + 4 * j4 + 2] = mx.z;  smax[r * 65 + 4 * j4 + 3] = mx.w;
    __syncthreads();

    if (t < HID) {
        float s = 0.f, m = -INFINITY;
        #pragma unroll
        for (int q = 0; q < 16; q++) {
            s += ssum[q * 65 + t];
            m = fmaxf(m, smax[q * 65 + t]);
        }
        gv[t]       = s / (float)(end - start);
        gv[HID + t] = m;
    }
    __syncthreads();

    if (t < HID) {
        float s = bc1[t];
        #pragma unroll 16
        for (int k = 0; k < 2 * HID; k++) s += gv[k] * Wc1[k * HID + t];
        hc[t] = fmaxf(s, 0.f);
    }
    __syncthreads();

    if (t < C_OUT) {
        float l = bc2[t];
        #pragma unroll 16
        for (int j = 0; j < HID; j++) l += hc[j] * Wc2[j * C_OUT + t];
        lg[t] = l;
    }
    __syncthreads();

    if (t == 0) {
        float m = -INFINITY;
        #pragma unroll
        for (int c = 0; c < C_OUT; c++) m = fmaxf(m, lg[c]);
        float se = 0.f;
        #pragma unroll
        for (int c = 0; c < C_OUT; c++) se += expf(lg[c] - m);
        s_lse = m + logf(se);
    }
    __syncthreads();
    if (t < C_OUT) out[g * C_OUT + t] = lg[t] - s_lse;
}

extern "C" void kernel_launch(void* const* d_in, const int* in_sizes, int n_in,
                              void* d_out, int out_size) {
    const float* x     = (const float*)d_in[0];
    const int*   ei    = (const int*)  d_in[1];
    const int*   batch = (const int*)  d_in[2];
    // d_in[3] = num_graphs (constant 128, unused)
    const float* W0    = (const float*)d_in[4];
    const float* Ws    = (const float*)d_in[5];
    const float* bs    = (const float*)d_in[6];
    const float* gamma = (const float*)d_in[7];
    const float* beta  = (const float*)d_in[8];
    const float* rmean = (const float*)d_in[9];
    const float* rvar  = (const float*)d_in[10];
    const float* Wc1   = (const float*)d_in[11];
    const float* bc1   = (const float*)d_in[12];
    const float* Wc2   = (const float*)d_in[13];
    const float* bc2   = (const float*)d_in[14];
    float* out = (float*)d_out;

    const int NB_N    = (N_NODES + 255) / 256;
    const int NB_E4   = (N_EDGES / 4 + 255) / 256;
    const int NB_GAT  = N_NODES / 8;           // 12500, 128-thread blocks
    const int NB_GEMM = (N_NODES + 127) / 128; // 782

    // zero-init counters via graph memset nodes
    void* p_ecnt = 0; void* p_tot = 0;
    cudaGetSymbolAddress(&p_ecnt, g_ecnt);
    cudaGetSymbolAddress(&p_tot,  g_tot);
    cudaMemsetAsync(p_ecnt, 0, N_NODES * sizeof(int));
    cudaMemsetAsync(p_tot,  0, sizeof(int));

    // CSR build (fill overlapped with layer-0 linear in one launch)
    k_deg      <<<NB_E4, 256>>>(ei);
    k_base     <<<NB_N, 256>>>();
    k_fill_lin0<<<NB_FILL + NB_L0, 256>>>(ei, x, W0);

    // layer 0 aggregate
    k_gather<<<NB_GAT, 128>>>(bs + 0 * HID, gamma + 0 * HID, beta + 0 * HID,
                              rmean + 0 * HID, rvar + 0 * HID, 1);
    // layer 1
    k_linh  <<<NB_GEMM, 256>>>(Ws + 0 * HID * HID);
    k_gather<<<NB_GAT, 128>>>(bs + 1 * HID, gamma + 1 * HID, beta + 1 * HID,
                              rmean + 1 * HID, rvar + 1 * HID, 1);
    // layer 2 (no relu)
    k_linh  <<<NB_GEMM, 256>>>(Ws + 1 * HID * HID);
    k_gather<<<NB_GAT, 128>>>(bs + 2 * HID, gamma + 2 * HID, beta + 2 * HID,
                              rmean + 2 * HID, rvar + 2 * HID, 0);

    // fused pooling + classifier
    k_poolcls<<<G_NUM, 256>>>(batch, Wc1, bc1, Wc2, bc2, out);
}